// round 1
// baseline (speedup 1.0000x reference)
#include <cuda_runtime.h>
#include <math.h>
#include <stdint.h>

#define BATCH 4
#define TT    4096
#define HD    2048
#define DD    128
#define LLEN  64
#define SSEG  64
#define NT    (BATCH*TT)     // 16384 rows
#define NSEG  (BATCH*SSEG)   // 256 segments
#define NCOL  257            // 128 H_mem + 128 Q_r + 1 eta
#define WS    320            // padded N (5 * 64)
#define SCALEF 0.08838834764831845f  // 1/sqrt(128)

// ----------------- device scratch (static, no allocs) -----------------
__device__ float g_mu[NT];
__device__ float g_rstd[NT];
__device__ float g_Wp[HD*WS];          // g ∘ W, zero-padded cols
__device__ float g_gW[WS];             // colsum of g∘W
__device__ float g_bproj[WS];          // b@W + per-col bias
__device__ float g_Hmem[(size_t)NT*DD];
__device__ float g_Qr[(size_t)NT*DD];
__device__ float g_eta[NT];
__device__ float g_Z[NSEG*DD];
__device__ float g_etaseg[NSEG];
__device__ float g_A[NSEG*DD];
__device__ float g_Mnew[BATCH*DD*DD];
__device__ float g_Mn[BATCH*DD*DD];
__device__ float g_normp[BATCH*DD];    // 512 partials (deterministic)
__device__ float g_divp[BATCH*DD];     // 512 partials

// ----------------- reduction helpers -----------------
__device__ __forceinline__ float blockSumG(float v, float* red) {
    int lane = threadIdx.x & 31, w = threadIdx.x >> 5;
    int nw = (blockDim.x + 31) >> 5;
    #pragma unroll
    for (int o = 16; o; o >>= 1) v += __shfl_xor_sync(0xffffffffu, v, o);
    if (lane == 0) red[w] = v;
    __syncthreads();
    float r = 0.f;
    for (int i = 0; i < nw; i++) r += red[i];
    __syncthreads();
    return r;
}

__device__ __forceinline__ float blockMaxG(float v, float* red) {
    int lane = threadIdx.x & 31, w = threadIdx.x >> 5;
    int nw = (blockDim.x + 31) >> 5;
    #pragma unroll
    for (int o = 16; o; o >>= 1) v = fmaxf(v, __shfl_xor_sync(0xffffffffu, v, o));
    if (lane == 0) red[w] = v;
    __syncthreads();
    float r = -3.4e38f;
    for (int i = 0; i < nw; i++) r = fmaxf(r, red[i]);
    __syncthreads();
    return r;
}

// ----------------- K0: prepare weights + fold layernorm -----------------
__global__ void prep_kernel(const float* __restrict__ ln_g, const float* __restrict__ ln_b,
                            const float* __restrict__ sp_w, const float* __restrict__ W_qkv,
                            const float* __restrict__ W_eta_w, const float* __restrict__ W_eta_b,
                            const float* __restrict__ sp_b) {
    __shared__ float red[8];
    int j = blockIdx.x;          // column 0..319
    int tid = threadIdx.x;       // 256 threads
    float sg = 0.f, sb = 0.f;
    for (int h = tid; h < HD; h += 256) {
        float w;
        if (j < 128)       w = sp_w[h*DD + j];
        else if (j < 256)  w = W_qkv[h*384 + 256 + (j - 128)];
        else if (j == 256) w = W_eta_w[h];
        else               w = 0.f;
        float g = ln_g[h], b = ln_b[h];
        g_Wp[(size_t)h*WS + j] = g * w;
        sg += g * w;
        sb += b * w;
    }
    sg = blockSumG(sg, red);
    sb = blockSumG(sb, red);
    if (tid == 0) {
        float bias = 0.f;
        if (j < 128)       bias = sp_b[j];
        else if (j == 256) bias = W_eta_b[0];
        g_gW[j] = sg;
        g_bproj[j] = sb + bias;
    }
}

// ----------------- K1: row stats (mu, rstd) over H -----------------
__global__ void stats_kernel(const float* __restrict__ H) {
    __shared__ float red[8];
    int r = blockIdx.x;
    int tid = threadIdx.x;
    const float4* row = (const float4*)(H + (size_t)r * HD);
    float s = 0.f, sq = 0.f;
    for (int i = tid; i < HD/4; i += 256) {
        float4 v = row[i];
        s  += v.x + v.y + v.z + v.w;
        sq += v.x*v.x + v.y*v.y + v.z*v.z + v.w*v.w;
    }
    s  = blockSumG(s, red);
    sq = blockSumG(sq, red);
    if (tid == 0) {
        float mu = s * (1.f/HD);
        float var = sq * (1.f/HD) - mu*mu;
        g_mu[r] = mu;
        g_rstd[r] = rsqrtf(var + 1e-5f);
    }
}

// ----------------- K2: GEMM raw-H[16384,2048] x Wp[2048,320] + LN epilogue -----------------
// BM=128, BN=64, BK=16, 256 threads, 8x4 microtile.
__global__ __launch_bounds__(256) void gemm_kernel(const float* __restrict__ H) {
    __shared__ float As[16][128];
    __shared__ float Bs[16][64];
    const int n0  = blockIdx.x * 64;
    const int m0  = blockIdx.y * 128;
    const int tid = threadIdx.x;

    const int ar0 = tid >> 2;            // A rows: ar0 and ar0+64
    const int ac  = (tid & 3) * 4;       // A cols (float4)
    const int br  = tid >> 4;            // B row 0..15
    const int bc  = (tid & 15) * 4;      // B cols (float4)
    const int tm  = (tid >> 4) * 8;      // micro row
    const int tn  = (tid & 15) * 4;      // micro col

    float acc[8][4];
    #pragma unroll
    for (int i = 0; i < 8; i++)
        #pragma unroll
        for (int j = 0; j < 4; j++) acc[i][j] = 0.f;

    for (int k0 = 0; k0 < HD; k0 += 16) {
        float4 va0 = *(const float4*)(H + (size_t)(m0 + ar0) * HD + k0 + ac);
        float4 va1 = *(const float4*)(H + (size_t)(m0 + ar0 + 64) * HD + k0 + ac);
        float4 vb  = *(const float4*)(&g_Wp[(size_t)(k0 + br) * WS + n0 + bc]);
        __syncthreads();
        As[ac+0][ar0] = va0.x; As[ac+1][ar0] = va0.y;
        As[ac+2][ar0] = va0.z; As[ac+3][ar0] = va0.w;
        As[ac+0][ar0+64] = va1.x; As[ac+1][ar0+64] = va1.y;
        As[ac+2][ar0+64] = va1.z; As[ac+3][ar0+64] = va1.w;
        *(float4*)&Bs[br][bc] = vb;
        __syncthreads();
        #pragma unroll
        for (int kk = 0; kk < 16; kk++) {
            float4 a0 = *(float4*)&As[kk][tm];
            float4 a1 = *(float4*)&As[kk][tm+4];
            float4 b  = *(float4*)&Bs[kk][tn];
            float av[8] = {a0.x,a0.y,a0.z,a0.w,a1.x,a1.y,a1.z,a1.w};
            float bv[4] = {b.x,b.y,b.z,b.w};
            #pragma unroll
            for (int i = 0; i < 8; i++)
                #pragma unroll
                for (int j = 0; j < 4; j++)
                    acc[i][j] += av[i] * bv[j];
        }
    }

    // epilogue: apply folded layernorm, route columns
    #pragma unroll
    for (int i = 0; i < 8; i++) {
        int t = m0 + tm + i;
        float mu = g_mu[t], rs = g_rstd[t];
        #pragma unroll
        for (int j = 0; j < 4; j++) {
            int jj = n0 + tn + j;
            if (jj < NCOL) {
                float v = rs * (acc[i][j] - mu * g_gW[jj]) + g_bproj[jj];
                if (jj < 128)      g_Hmem[(size_t)t*DD + jj] = v;
                else if (jj < 256) g_Qr[(size_t)t*DD + (jj-128)] = v;
                else               g_eta[t] = v;
            }
        }
    }
}

// ----------------- K3: per-segment summary softmax + Z_seg + eta_seg -----------------
__global__ void seg_kernel(const float* __restrict__ sum_q) {
    __shared__ float Hs[LLEN*129];
    __shared__ float qs[DD];
    __shared__ float sc[LLEN];
    int seg = blockIdx.x;
    int tid = threadIdx.x;   // 128
    int base = seg * LLEN;   // token row base
    for (int l = 0; l < LLEN; l++)
        Hs[l*129 + tid] = g_Hmem[(size_t)(base + l)*DD + tid];
    qs[tid] = sum_q[tid];
    __syncthreads();
    if (tid < LLEN) {
        float s = 0.f;
        for (int d = 0; d < DD; d++) s += qs[d] * Hs[tid*129 + d];
        sc[tid] = s * SCALEF;
    }
    __syncthreads();
    float mx = -3.4e38f;
    for (int l = 0; l < LLEN; l++) mx = fmaxf(mx, sc[l]);
    __syncthreads();
    if (tid < LLEN) sc[tid] = expf(sc[tid] - mx);
    __syncthreads();
    float sum = 0.f;
    for (int l = 0; l < LLEN; l++) sum += sc[l];
    float inv = 1.f / sum;
    float z = 0.f;
    for (int l = 0; l < LLEN; l++) z += sc[l] * Hs[l*129 + tid];
    g_Z[seg*DD + tid] = z * inv;
    // eta_seg = sigmoid(max eta_token)  (sigmoid is monotone)
    __syncthreads();
    if (tid < LLEN) sc[tid] = g_eta[base + tid];
    __syncthreads();
    float em = -3.4e38f;
    for (int l = 0; l < LLEN; l++) em = fmaxf(em, sc[l]);
    if (tid == 0) g_etaseg[seg] = 1.f / (1.f + expf(-em));
}

// ----------------- K4: attention over memory slots (A = softmax(Z·M)) -----------------
__global__ void scoreA_kernel(const float* __restrict__ M, const float* __restrict__ temp) {
    __shared__ float Zs[DD];
    __shared__ float sb[DD];
    int seg = blockIdx.x;
    int tid = threadIdx.x;   // 128 = one memory slot each
    int b = seg >> 6;
    Zs[tid] = g_Z[seg*DD + tid];
    __syncthreads();
    const float* mrow = M + (size_t)(b*DD + tid) * DD;
    float s = 0.f;
    for (int d = 0; d < DD; d++) s += Zs[d] * mrow[d];
    s *= SCALEF * expf(temp[0]);
    sb[tid] = s;
    __syncthreads();
    float mx = -3.4e38f;
    for (int k = 0; k < DD; k++) mx = fmaxf(mx, sb[k]);
    __syncthreads();
    float e = expf(s - mx);
    sb[tid] = e;
    __syncthreads();
    float sum = 0.f;
    for (int k = 0; k < DD; k++) sum += sb[k];
    g_A[seg*DD + tid] = e / sum;
}

// ----------------- K5: DeltaM, M_new, Mn rows, norm_sq partials -----------------
__global__ void update_kernel(const float* __restrict__ M, const float* __restrict__ eta_ch) {
    __shared__ float ae[LLEN];
    __shared__ float etas[LLEN];
    __shared__ float red[4];
    int k = blockIdx.x, b = blockIdx.y;
    int tid = threadIdx.x;   // 128 = d
    if (tid < SSEG) {
        float e = g_etaseg[b*SSEG + tid];
        etas[tid] = e;
        ae[tid] = g_A[(size_t)(b*SSEG + tid)*DD + k] * e;
    }
    __syncthreads();
    float eavg = 0.f;
    for (int s = 0; s < SSEG; s++) eavg += etas[s];
    eavg *= (1.f / SSEG);
    float delta = 0.f;
    for (int s = 0; s < SSEG; s++)
        delta += ae[s] * g_Z[(size_t)(b*SSEG + s)*DD + tid];
    float mold = M[(size_t)(b*DD + k)*DD + tid];
    float gate = eavg * (1.f / (1.f + expf(-eta_ch[tid])));
    float mnew = (1.f - gate) * mold + delta * (1.f / SSEG);

    float ns = blockSumG(delta * delta, red);
    if (tid == 0) g_normp[b*DD + k] = ns;
    float nn = blockSumG(mnew * mnew, red);
    float inv = 1.f / fmaxf(sqrtf(nn), 1e-12f);
    size_t idx = (size_t)(b*DD + k)*DD + tid;
    g_Mnew[idx] = mnew;
    g_Mn[idx]   = mnew * inv;
}

// ----------------- K6: diversity loss partials -----------------
__global__ void div_kernel() {
    __shared__ float mks[DD];
    __shared__ float red[4];
    int k = blockIdx.x, b = blockIdx.y;
    int tid = threadIdx.x;   // 128 = j
    mks[tid] = g_Mn[(size_t)(b*DD + k)*DD + tid];
    __syncthreads();
    const float* mj = g_Mn + (size_t)(b*DD + tid)*DD;
    float s = 0.f;
    for (int d = 0; d < DD; d++) s += mks[d] * mj[d];
    float v = (tid == k) ? 0.f : s * s;
    float tot = blockSumG(v, red);
    if (tid == 0) g_divp[b*DD + k] = tot;
}

// ----------------- K7: finalize loss (deterministic reduce) -----------------
__global__ void finalize_kernel(float* __restrict__ out, int out_size) {
    __shared__ float red[8];
    float n = 0.f, d = 0.f;
    for (int i = threadIdx.x; i < BATCH*DD; i += 256) {
        n += g_normp[i];
        d += g_divp[i];
    }
    n = blockSumG(n, red);
    d = blockSumG(d, red);
    if (threadIdx.x == 0) {
        float norm_sq = n * (1.f / SSEG);
        float div = d / (float)(BATCH*DD*DD);
        out[out_size - 1] = norm_sq * 0.01f + div * 0.1f;
    }
}

// ----------------- K8: read attention C = softmax(2*Qr·Mnew) @ Mnew -----------------
__global__ void read_kernel(float* __restrict__ out) {
    extern __shared__ float sm[];
    float* Ms  = sm;                 // 128*129
    float* qs  = sm + DD*129;        // 128
    float* ar  = qs + DD;            // 128
    float* red = ar + DD;            // 8
    int tid = threadIdx.x;           // 128
    int t0 = blockIdx.x * 32;
    int b = t0 >> 12;
    for (int k = 0; k < DD; k++)
        Ms[k*129 + tid] = g_Mnew[(size_t)(b*DD + k)*DD + tid];
    __syncthreads();
    for (int tk = 0; tk < 32; tk++) {
        int t = t0 + tk;
        qs[tid] = g_Qr[(size_t)t*DD + tid];
        __syncthreads();
        float s = 0.f;
        #pragma unroll 8
        for (int d = 0; d < DD; d++) s += qs[d] * Ms[tid*129 + d];
        s *= 2.0f;
        float mx = blockMaxG(s, red);
        float e = expf(s - mx);
        float sum = blockSumG(e, red);
        ar[tid] = e / sum;
        __syncthreads();
        float c = 0.f;
        #pragma unroll 8
        for (int k = 0; k < DD; k++) c += ar[k] * Ms[k*129 + tid];
        out[(size_t)t*DD + tid] = c;
        __syncthreads();
    }
}

// ----------------- launch -----------------
extern "C" void kernel_launch(void* const* d_in, const int* in_sizes, int n_in,
                              void* d_out, int out_size) {
    const float* H       = (const float*)d_in[0];
    const float* M       = (const float*)d_in[1];
    const float* ln_g    = (const float*)d_in[2];
    const float* ln_b    = (const float*)d_in[3];
    const float* W_eta_w = (const float*)d_in[4];
    const float* W_eta_b = (const float*)d_in[5];
    const float* sum_q   = (const float*)d_in[6];
    const float* sp_w    = (const float*)d_in[7];
    const float* sp_b    = (const float*)d_in[8];
    const float* eta_ch  = (const float*)d_in[9];
    const float* temp    = (const float*)d_in[10];
    const float* W_qkv   = (const float*)d_in[11];
    float* out = (float*)d_out;

    int smem_read = (DD*129 + DD + DD + 8) * (int)sizeof(float);
    cudaFuncSetAttribute(read_kernel, cudaFuncAttributeMaxDynamicSharedMemorySize, smem_read);

    prep_kernel<<<WS, 256>>>(ln_g, ln_b, sp_w, W_qkv, W_eta_w, W_eta_b, sp_b);
    stats_kernel<<<NT, 256>>>(H);
    gemm_kernel<<<dim3(WS/64, NT/128), 256>>>(H);
    seg_kernel<<<NSEG, 128>>>(sum_q);
    scoreA_kernel<<<NSEG, 128>>>(M, temp);
    update_kernel<<<dim3(DD, BATCH), 128>>>(M, eta_ch);
    div_kernel<<<dim3(DD, BATCH), 128>>>();
    finalize_kernel<<<1, 256>>>(out, out_size);
    read_kernel<<<NT/32, 128, smem_read>>>(out);
}

// round 7
// speedup vs baseline: 1.4551x; 1.4551x over previous
#include <cuda_runtime.h>
#include <cuda_bf16.h>
#include <math.h>
#include <stdint.h>

#define BATCH 4
#define TT    4096
#define HD    2048
#define DD    128
#define LLEN  64
#define SSEG  64
#define NT    (BATCH*TT)     // 16384 rows
#define NSEG  (BATCH*SSEG)   // 256 segments
#define NB    256            // GEMM N (128 Hmem + 128 Qr)
#define KP    (3*HD)         // 6144 tripled K (hi/lo compensated bf16)
#define NSTG  (KP/32)        // 192 stages of BK=32
#define SCALEF 0.08838834764831845f

// ----------------- device scratch (static, no allocs) -----------------
__device__ __align__(16) __nv_bfloat16 g_A3[(size_t)NT*KP];   // ~201 MB
__device__ __align__(16) __nv_bfloat16 g_B3[(size_t)NB*KP];   // ~3.1 MB
__device__ float g_weta[HD];           // ln_g * W_eta_w
__device__ float g_mu[NT];
__device__ float g_rstd[NT];
__device__ float g_gW[NB+1];
__device__ float g_bproj[NB+1];
__device__ float g_Hmem[(size_t)NT*DD];
__device__ float g_Qr[(size_t)NT*DD];
__device__ float g_eta[NT];
__device__ float g_Z[NSEG*DD];
__device__ float g_etaseg[NSEG];
__device__ float g_A[NSEG*DD];
__device__ float g_Mnew[BATCH*DD*DD];
__device__ float g_Mn[BATCH*DD*DD];
__device__ float g_normp[BATCH*DD];
__device__ float g_divp[BATCH*DD];

// ----------------- helpers -----------------
__device__ __forceinline__ uint32_t smem_u32(const void* p) {
    uint32_t a;
    asm("{ .reg .u64 t; cvta.to.shared.u64 t, %1; cvt.u32.u64 %0, t; }" : "=r"(a) : "l"(p));
    return a;
}
#define CP_ASYNC16(dst, src) \
    asm volatile("cp.async.cg.shared.global [%0], [%1], 16;" :: "r"(dst), "l"(src) : "memory")
#define CP_COMMIT() asm volatile("cp.async.commit_group;" ::: "memory")
#define CP_WAIT2()  asm volatile("cp.async.wait_group 2;" ::: "memory")

__device__ __forceinline__ void mma16816(float* d, const uint32_t* a, const uint32_t* b) {
    asm volatile("mma.sync.aligned.m16n8k16.row.col.f32.bf16.bf16.f32 "
        "{%0,%1,%2,%3}, {%4,%5,%6,%7}, {%8,%9}, {%0,%1,%2,%3};"
        : "+f"(d[0]), "+f"(d[1]), "+f"(d[2]), "+f"(d[3])
        : "r"(a[0]), "r"(a[1]), "r"(a[2]), "r"(a[3]), "r"(b[0]), "r"(b[1]));
}

__device__ __forceinline__ float blockSumG(float v, float* red) {
    int lane = threadIdx.x & 31, w = threadIdx.x >> 5;
    int nw = (blockDim.x + 31) >> 5;
    #pragma unroll
    for (int o = 16; o; o >>= 1) v += __shfl_xor_sync(0xffffffffu, v, o);
    if (lane == 0) red[w] = v;
    __syncthreads();
    float r = 0.f;
    for (int i = 0; i < nw; i++) r += red[i];
    __syncthreads();
    return r;
}
__device__ __forceinline__ float blockMaxG(float v, float* red) {
    int lane = threadIdx.x & 31, w = threadIdx.x >> 5;
    int nw = (blockDim.x + 31) >> 5;
    #pragma unroll
    for (int o = 16; o; o >>= 1) v = fmaxf(v, __shfl_xor_sync(0xffffffffu, v, o));
    if (lane == 0) red[w] = v;
    __syncthreads();
    float r = -3.4e38f;
    for (int i = 0; i < nw; i++) r = fmaxf(r, red[i]);
    __syncthreads();
    return r;
}

// ----------------- K0: build B3 (LN-folded weights, hi/lo tripled) + eta vector -----------------
__global__ void bprep_kernel(const float* __restrict__ ln_g, const float* __restrict__ ln_b,
                             const float* __restrict__ sp_w, const float* __restrict__ W_qkv,
                             const float* __restrict__ W_eta_w, const float* __restrict__ W_eta_b,
                             const float* __restrict__ sp_b) {
    __shared__ float red[8];
    int n = blockIdx.x, tid = threadIdx.x;    // 257 blocks x 256 threads
    float f[8];
    float sg = 0.f, sb = 0.f;
    #pragma unroll
    for (int i = 0; i < 8; i++) {
        int h = tid * 8 + i;
        float w;
        if (n < 128)       w = sp_w[h*DD + n];
        else if (n < 256)  w = W_qkv[h*384 + 256 + (n - 128)];
        else               w = W_eta_w[h];
        float g = ln_g[h], b = ln_b[h];
        f[i] = g * w;
        sg += g * w;
        sb += b * w;
    }
    sg = blockSumG(sg, red);
    sb = blockSumG(sb, red);
    if (tid == 0) {
        float bias = 0.f;
        if (n < 128)       bias = sp_b[n];
        else if (n == 256) bias = W_eta_b[0];
        g_gW[n] = sg;
        g_bproj[n] = sb + bias;
    }
    if (n == 256) {   // eta weight vector stays fp32 (fused dot in conv kernel)
        #pragma unroll
        for (int i = 0; i < 8; i++) g_weta[tid*8 + i] = f[i];
        return;
    }
    __nv_bfloat16 hi[8], lo[8];
    #pragma unroll
    for (int i = 0; i < 8; i++) {
        hi[i] = __float2bfloat16_rn(f[i]);
        lo[i] = __float2bfloat16_rn(f[i] - __bfloat162float(hi[i]));
    }
    union { uint4 q[3]; __nv_bfloat162 h2[12]; } pk;
    #pragma unroll
    for (int j = 0; j < 4; j++) {   // B pattern per k: (hi, hi, lo)
        pk.h2[3*j+0] = __halves2bfloat162(hi[2*j],   hi[2*j]);
        pk.h2[3*j+1] = __halves2bfloat162(lo[2*j],   hi[2*j+1]);
        pk.h2[3*j+2] = __halves2bfloat162(hi[2*j+1], lo[2*j+1]);
    }
    uint4* dst = (uint4*)(g_B3 + (size_t)n * KP) + tid * 3;
    dst[0] = pk.q[0]; dst[1] = pk.q[1]; dst[2] = pk.q[2];
}

// ----------------- K1: LN stats + eta dot + hi/lo tripled conversion of H -----------------
__global__ void conv_kernel(const float* __restrict__ H) {
    __shared__ float red[8];
    int r = blockIdx.x, tid = threadIdx.x;    // 256 threads
    const float4* row = (const float4*)(H + (size_t)r * HD);
    float4 v0 = row[tid * 2], v1 = row[tid * 2 + 1];
    float f[8] = {v0.x, v0.y, v0.z, v0.w, v1.x, v1.y, v1.z, v1.w};
    float s = 0.f, sq = 0.f, dot = 0.f;
    #pragma unroll
    for (int i = 0; i < 8; i++) {
        s += f[i]; sq += f[i] * f[i];
        dot += f[i] * g_weta[tid*8 + i];
    }
    s   = blockSumG(s, red);
    sq  = blockSumG(sq, red);
    dot = blockSumG(dot, red);
    if (tid == 0) {
        float mu = s * (1.f / HD);
        float var = sq * (1.f / HD) - mu * mu;
        float rs = rsqrtf(var + 1e-5f);
        g_mu[r] = mu;
        g_rstd[r] = rs;
        g_eta[r] = rs * (dot - mu * g_gW[256]) + g_bproj[256];
    }
    __nv_bfloat16 hi[8], lo[8];
    #pragma unroll
    for (int i = 0; i < 8; i++) {
        hi[i] = __float2bfloat16_rn(f[i]);
        lo[i] = __float2bfloat16_rn(f[i] - __bfloat162float(hi[i]));
    }
    union { uint4 q[3]; __nv_bfloat162 h2[12]; } pk;
    #pragma unroll
    for (int j = 0; j < 4; j++) {   // A pattern per k: (hi, lo, hi)
        pk.h2[3*j+0] = __halves2bfloat162(hi[2*j],   lo[2*j]);
        pk.h2[3*j+1] = __halves2bfloat162(hi[2*j],   hi[2*j+1]);
        pk.h2[3*j+2] = __halves2bfloat162(lo[2*j+1], hi[2*j+1]);
    }
    uint4* dst = (uint4*)(g_A3 + (size_t)r * KP) + tid * 3;
    dst[0] = pk.q[0]; dst[1] = pk.q[1]; dst[2] = pk.q[2];
}

// ----------------- K2: HMMA GEMM [16384 x 6144] x [256 x 6144]^T + LN epilogue -----------------
// BM=128, BN=64, BK=32(bf16), 3-stage cp.async pipeline, 8 warps (4 M x 2 N), warp tile 32x32.
#define ASTRIDE 40   // bf16 elems per smem row (80 B, conflict-free fragment LDS)
__global__ void __launch_bounds__(256) mma_kernel() {
    __shared__ __align__(16) __nv_bfloat16 sA[3][128*ASTRIDE];
    __shared__ __align__(16) __nv_bfloat16 sB[3][64*ASTRIDE];
    const int tid = threadIdx.x;
    const int wid = tid >> 5, lane = tid & 31;
    const int warp_m = wid & 3, warp_n = wid >> 2;
    const int g = lane >> 2, t = lane & 3;
    const int m0 = blockIdx.y * 128, n0 = blockIdx.x * 64;

    const uint32_t sAb = smem_u32(sA[0]);
    const uint32_t sBb = smem_u32(sB[0]);
    // precomputed per-thread load coords
    const int ar = tid >> 2, ac = tid & 3;        // A: rows ar, ar+64 (2 chunks)
    const int br = tid >> 2, bc = tid & 3;        // B: 1 chunk
    const __nv_bfloat16* gA0 = g_A3 + (size_t)(m0 + ar) * KP + ac * 8;
    const __nv_bfloat16* gA1 = g_A3 + (size_t)(m0 + ar + 64) * KP + ac * 8;
    const __nv_bfloat16* gB0 = g_B3 + (size_t)(n0 + br) * KP + bc * 8;

    float acc[2][4][4];
    #pragma unroll
    for (int mi = 0; mi < 2; mi++)
        #pragma unroll
        for (int ni = 0; ni < 4; ni++)
            #pragma unroll
            for (int j = 0; j < 4; j++) acc[mi][ni][j] = 0.f;

    #define ISSUE(s, b) do { \
        uint32_t dA = sAb + (b) * (128*ASTRIDE*2); \
        uint32_t dB = sBb + (b) * (64*ASTRIDE*2); \
        CP_ASYNC16(dA + ar * (ASTRIDE*2) + ac * 16, gA0 + (size_t)(s) * 32); \
        CP_ASYNC16(dA + (ar + 64) * (ASTRIDE*2) + ac * 16, gA1 + (size_t)(s) * 32); \
        CP_ASYNC16(dB + br * (ASTRIDE*2) + bc * 16, gB0 + (size_t)(s) * 32); \
    } while (0)

    ISSUE(0, 0); CP_COMMIT();
    ISSUE(1, 1); CP_COMMIT();

    int buf = 0;
    for (int i = 0; i < NSTG; i++) {
        if (i + 2 < NSTG) {
            int nb = buf + 2; if (nb >= 3) nb -= 3;
            ISSUE(i + 2, nb);
        }
        CP_COMMIT();
        CP_WAIT2();
        __syncthreads();

        const __nv_bfloat16* bA = sA[buf];
        const __nv_bfloat16* bB = sB[buf];
        #pragma unroll
        for (int kk = 0; kk < 2; kk++) {
            uint32_t a[2][4], b[4][2];
            #pragma unroll
            for (int mi = 0; mi < 2; mi++) {
                const __nv_bfloat16* p = bA + (warp_m*32 + mi*16 + g) * ASTRIDE + kk*16 + t*2;
                a[mi][0] = *(const uint32_t*)(p);
                a[mi][1] = *(const uint32_t*)(p + 8*ASTRIDE);
                a[mi][2] = *(const uint32_t*)(p + 8);
                a[mi][3] = *(const uint32_t*)(p + 8*ASTRIDE + 8);
            }
            #pragma unroll
            for (int ni = 0; ni < 4; ni++) {
                const __nv_bfloat16* p = bB + (warp_n*32 + ni*8 + g) * ASTRIDE + kk*16 + t*2;
                b[ni][0] = *(const uint32_t*)(p);
                b[ni][1] = *(const uint32_t*)(p + 8);
            }
            #pragma unroll
            for (int mi = 0; mi < 2; mi++)
                #pragma unroll
                for (int ni = 0; ni < 4; ni++)
                    mma16816(acc[mi][ni], a[mi], b[ni]);
        }
        __syncthreads();
        if (++buf == 3) buf = 0;
    }

    // epilogue: folded layernorm + column routing
    #pragma unroll
    for (int mi = 0; mi < 2; mi++) {
        int r0 = m0 + warp_m*32 + mi*16 + g;
        int r1 = r0 + 8;
        float mu0 = g_mu[r0], rs0 = g_rstd[r0];
        float mu1 = g_mu[r1], rs1 = g_rstd[r1];
        #pragma unroll
        for (int ni = 0; ni < 4; ni++) {
            int c0 = n0 + warp_n*32 + ni*8 + t*2;
            #pragma unroll
            for (int j = 0; j < 2; j++) {
                int col = c0 + j;
                float gw = g_gW[col], bp = g_bproj[col];
                float v0 = rs0 * (acc[mi][ni][j]     - mu0 * gw) + bp;
                float v1 = rs1 * (acc[mi][ni][2 + j] - mu1 * gw) + bp;
                if (col < 128) {
                    g_Hmem[(size_t)r0*DD + col] = v0;
                    g_Hmem[(size_t)r1*DD + col] = v1;
                } else {
                    g_Qr[(size_t)r0*DD + col - 128] = v0;
                    g_Qr[(size_t)r1*DD + col - 128] = v1;
                }
            }
        }
    }
}

// ----------------- K3: per-segment summary softmax + Z_seg + eta_seg -----------------
__global__ void seg_kernel(const float* __restrict__ sum_q) {
    __shared__ float Hs[LLEN*129];
    __shared__ float qs[DD];
    __shared__ float sc[LLEN];
    int seg = blockIdx.x;
    int tid = threadIdx.x;   // 128
    int base = seg * LLEN;
    for (int l = 0; l < LLEN; l++)
        Hs[l*129 + tid] = g_Hmem[(size_t)(base + l)*DD + tid];
    qs[tid] = sum_q[tid];
    __syncthreads();
    if (tid < LLEN) {
        float s = 0.f;
        for (int d = 0; d < DD; d++) s += qs[d] * Hs[tid*129 + d];
        sc[tid] = s * SCALEF;
    }
    __syncthreads();
    float mx = -3.4e38f;
    for (int l = 0; l < LLEN; l++) mx = fmaxf(mx, sc[l]);
    __syncthreads();
    if (tid < LLEN) sc[tid] = expf(sc[tid] - mx);
    __syncthreads();
    float sum = 0.f;
    for (int l = 0; l < LLEN; l++) sum += sc[l];
    float inv = 1.f / sum;
    float z = 0.f;
    for (int l = 0; l < LLEN; l++) z += sc[l] * Hs[l*129 + tid];
    g_Z[seg*DD + tid] = z * inv;
    __syncthreads();
    if (tid < LLEN) sc[tid] = g_eta[base + tid];
    __syncthreads();
    float em = -3.4e38f;
    for (int l = 0; l < LLEN; l++) em = fmaxf(em, sc[l]);
    if (tid == 0) g_etaseg[seg] = 1.f / (1.f + expf(-em));
}

// ----------------- K4: A = softmax(Z . M * scale * exp(temp)) -----------------
__global__ void scoreA_kernel(const float* __restrict__ M, const float* __restrict__ temp) {
    __shared__ float Zs[DD];
    __shared__ float sbuf[DD];
    int seg = blockIdx.x;
    int tid = threadIdx.x;
    int b = seg >> 6;
    Zs[tid] = g_Z[seg*DD + tid];
    __syncthreads();
    const float* mrow = M + (size_t)(b*DD + tid) * DD;
    float s = 0.f;
    for (int d = 0; d < DD; d++) s += Zs[d] * mrow[d];
    s *= SCALEF * expf(temp[0]);
    sbuf[tid] = s;
    __syncthreads();
    float mx = -3.4e38f;
    for (int k = 0; k < DD; k++) mx = fmaxf(mx, sbuf[k]);
    __syncthreads();
    float e = expf(s - mx);
    sbuf[tid] = e;
    __syncthreads();
    float sum = 0.f;
    for (int k = 0; k < DD; k++) sum += sbuf[k];
    g_A[seg*DD + tid] = e / sum;
}

// ----------------- K5: DeltaM, M_new, Mn, norm_sq partials -----------------
__global__ void update_kernel(const float* __restrict__ M, const float* __restrict__ eta_ch) {
    __shared__ float ae[LLEN];
    __shared__ float etas[LLEN];
    __shared__ float red[4];
    int k = blockIdx.x, b = blockIdx.y;
    int tid = threadIdx.x;
    if (tid < SSEG) {
        float e = g_etaseg[b*SSEG + tid];
        etas[tid] = e;
        ae[tid] = g_A[(size_t)(b*SSEG + tid)*DD + k] * e;
    }
    __syncthreads();
    float eavg = 0.f;
    for (int s = 0; s < SSEG; s++) eavg += etas[s];
    eavg *= (1.f / SSEG);
    float delta = 0.f;
    for (int s = 0; s < SSEG; s++)
        delta += ae[s] * g_Z[(size_t)(b*SSEG + s)*DD + tid];
    float mold = M[(size_t)(b*DD + k)*DD + tid];
    float gate = eavg * (1.f / (1.f + expf(-eta_ch[tid])));
    float mnew = (1.f - gate) * mold + delta * (1.f / SSEG);

    float ns = blockSumG(delta * delta, red);
    if (tid == 0) g_normp[b*DD + k] = ns;
    float nn = blockSumG(mnew * mnew, red);
    float inv = 1.f / fmaxf(sqrtf(nn), 1e-12f);
    size_t idx = (size_t)(b*DD + k)*DD + tid;
    g_Mnew[idx] = mnew;
    g_Mn[idx]   = mnew * inv;
}

// ----------------- K6: diversity loss partials -----------------
__global__ void div_kernel() {
    __shared__ float mks[DD];
    __shared__ float red[4];
    int k = blockIdx.x, b = blockIdx.y;
    int tid = threadIdx.x;
    mks[tid] = g_Mn[(size_t)(b*DD + k)*DD + tid];
    __syncthreads();
    const float* mj = g_Mn + (size_t)(b*DD + tid)*DD;
    float s = 0.f;
    for (int d = 0; d < DD; d++) s += mks[d] * mj[d];
    float v = (tid == k) ? 0.f : s * s;
    float tot = blockSumG(v, red);
    if (tid == 0) g_divp[b*DD + k] = tot;
}

// ----------------- K7: finalize loss -----------------
__global__ void finalize_kernel(float* __restrict__ out, int out_size) {
    __shared__ float red[8];
    float n = 0.f, d = 0.f;
    for (int i = threadIdx.x; i < BATCH*DD; i += 256) {
        n += g_normp[i];
        d += g_divp[i];
    }
    n = blockSumG(n, red);
    d = blockSumG(d, red);
    if (threadIdx.x == 0) {
        float norm_sq = n * (1.f / SSEG);
        float div = d / (float)(BATCH*DD*DD);
        out[out_size - 1] = norm_sq * 0.01f + div * 0.1f;
    }
}

// ----------------- K8: read attention -----------------
__global__ void read_kernel(float* __restrict__ out) {
    extern __shared__ float sm[];
    float* Ms  = sm;
    float* qs  = sm + DD*129;
    float* ar  = qs + DD;
    float* red = ar + DD;
    int tid = threadIdx.x;
    int t0 = blockIdx.x * 32;
    int b = t0 >> 12;
    for (int k = 0; k < DD; k++)
        Ms[k*129 + tid] = g_Mnew[(size_t)(b*DD + k)*DD + tid];
    __syncthreads();
    for (int tk = 0; tk < 32; tk++) {
        int t = t0 + tk;
        qs[tid] = g_Qr[(size_t)t*DD + tid];
        __syncthreads();
        float s = 0.f;
        #pragma unroll 8
        for (int d = 0; d < DD; d++) s += qs[d] * Ms[tid*129 + d];
        s *= 2.0f;
        float mx = blockMaxG(s, red);
        float e = expf(s - mx);
        float sum = blockSumG(e, red);
        ar[tid] = e / sum;
        __syncthreads();
        float c = 0.f;
        #pragma unroll 8
        for (int k = 0; k < DD; k++) c += ar[k] * Ms[k*129 + tid];
        out[(size_t)t*DD + tid] = c;
        __syncthreads();
    }
}

// ----------------- launch -----------------
extern "C" void kernel_launch(void* const* d_in, const int* in_sizes, int n_in,
                              void* d_out, int out_size) {
    const float* H       = (const float*)d_in[0];
    const float* M       = (const float*)d_in[1];
    const float* ln_g    = (const float*)d_in[2];
    const float* ln_b    = (const float*)d_in[3];
    const float* W_eta_w = (const float*)d_in[4];
    const float* W_eta_b = (const float*)d_in[5];
    const float* sum_q   = (const float*)d_in[6];
    const float* sp_w    = (const float*)d_in[7];
    const float* sp_b    = (const float*)d_in[8];
    const float* eta_ch  = (const float*)d_in[9];
    const float* temp    = (const float*)d_in[10];
    const float* W_qkv   = (const float*)d_in[11];
    float* out = (float*)d_out;

    int smem_read = (DD*129 + DD + DD + 8) * (int)sizeof(float);
    cudaFuncSetAttribute(read_kernel, cudaFuncAttributeMaxDynamicSharedMemorySize, smem_read);

    bprep_kernel<<<NB + 1, 256>>>(ln_g, ln_b, sp_w, W_qkv, W_eta_w, W_eta_b, sp_b);
    conv_kernel<<<NT, 256>>>(H);
    mma_kernel<<<dim3(NB/64, NT/128), 256>>>();
    seg_kernel<<<NSEG, 128>>>(sum_q);
    scoreA_kernel<<<NSEG, 128>>>(M, temp);
    update_kernel<<<dim3(DD, BATCH), 128>>>(M, eta_ch);
    div_kernel<<<dim3(DD, BATCH), 128>>>();
    finalize_kernel<<<1, 256>>>(out, out_size);
    read_kernel<<<NT/32, 128, smem_read>>>(out);
}

// round 10
// speedup vs baseline: 1.8502x; 1.2715x over previous
#include <cuda_runtime.h>
#include <cuda_bf16.h>
#include <math.h>
#include <stdint.h>

#define BATCH 4
#define TT    4096
#define HD    2048
#define DD    128
#define LLEN  64
#define SSEG  64
#define NT    (BATCH*TT)     // 16384 rows
#define NSEG  (BATCH*SSEG)   // 256 segments
#define NB    256            // GEMM N (128 Hmem + 128 Qr)
#define KP    (3*HD)         // 6144 tripled K (hi/lo compensated bf16)
#define STAGES 128           // HD/16 fp32 per stage -> 48 bf16 per stage
#define STR   56             // smem row stride in bf16 (112 B, conflict-free)
#define SCALEF 0.08838834764831845f

// ----------------- device scratch (static, no allocs) -----------------
__device__ __align__(16) __nv_bfloat16 g_B3[(size_t)NB*KP];   // ~3.1 MB
__device__ float g_weta[HD];           // ln_g * W_eta_w
__device__ float g_gW[NB+1];
__device__ float g_bproj[NB+1];
__device__ float g_Hmem[(size_t)NT*DD];
__device__ float g_Qr[(size_t)NT*DD];
__device__ float g_eta[NT];
__device__ float g_Z[NSEG*DD];
__device__ float g_etaseg[NSEG];
__device__ float g_A[NSEG*DD];
__device__ float g_Mnew[BATCH*DD*DD];
__device__ float g_Mn[BATCH*DD*DD];
__device__ float g_normp[BATCH*DD];
__device__ float g_divp[BATCH*DD];

// ----------------- helpers -----------------
__device__ __forceinline__ uint32_t smem_u32(const void* p) {
    uint32_t a;
    asm("{ .reg .u64 t; cvta.to.shared.u64 t, %1; cvt.u32.u64 %0, t; }" : "=r"(a) : "l"(p));
    return a;
}
#define CP_ASYNC16(dst, src) \
    asm volatile("cp.async.cg.shared.global [%0], [%1], 16;" :: "r"(dst), "l"(src) : "memory")
#define CP_COMMIT() asm volatile("cp.async.commit_group;" ::: "memory")
#define CP_WAIT0()  asm volatile("cp.async.wait_group 0;" ::: "memory")

__device__ __forceinline__ void mma16816(float* d, const uint32_t* a, const uint32_t* b) {
    asm volatile("mma.sync.aligned.m16n8k16.row.col.f32.bf16.bf16.f32 "
        "{%0,%1,%2,%3}, {%4,%5,%6,%7}, {%8,%9}, {%0,%1,%2,%3};"
        : "+f"(d[0]), "+f"(d[1]), "+f"(d[2]), "+f"(d[3])
        : "r"(a[0]), "r"(a[1]), "r"(a[2]), "r"(a[3]), "r"(b[0]), "r"(b[1]));
}

__device__ __forceinline__ float blockSumG(float v, float* red) {
    int lane = threadIdx.x & 31, w = threadIdx.x >> 5;
    int nw = (blockDim.x + 31) >> 5;
    #pragma unroll
    for (int o = 16; o; o >>= 1) v += __shfl_xor_sync(0xffffffffu, v, o);
    if (lane == 0) red[w] = v;
    __syncthreads();
    float r = 0.f;
    for (int i = 0; i < nw; i++) r += red[i];
    __syncthreads();
    return r;
}

// ----------------- K0: build B3 (LN-folded weights, hi/lo tripled) + eta vector -----------------
__global__ void bprep_kernel(const float* __restrict__ ln_g, const float* __restrict__ ln_b,
                             const float* __restrict__ sp_w, const float* __restrict__ W_qkv,
                             const float* __restrict__ W_eta_w, const float* __restrict__ W_eta_b,
                             const float* __restrict__ sp_b) {
    __shared__ float red[8];
    int n = blockIdx.x, tid = threadIdx.x;    // 257 blocks x 256 threads
    float f[8];
    float sg = 0.f, sb = 0.f;
    #pragma unroll
    for (int i = 0; i < 8; i++) {
        int h = tid * 8 + i;
        float w;
        if (n < 128)       w = sp_w[h*DD + n];
        else if (n < 256)  w = W_qkv[h*384 + 256 + (n - 128)];
        else               w = W_eta_w[h];
        float g = ln_g[h], b = ln_b[h];
        f[i] = g * w;
        sg += g * w;
        sb += b * w;
    }
    sg = blockSumG(sg, red);
    sb = blockSumG(sb, red);
    if (tid == 0) {
        float bias = 0.f;
        if (n < 128)       bias = sp_b[n];
        else if (n == 256) bias = W_eta_b[0];
        g_gW[n] = sg;
        g_bproj[n] = sb + bias;
    }
    if (n == 256) {   // eta weight vector stays fp32 (fused dot in GEMM)
        #pragma unroll
        for (int i = 0; i < 8; i++) g_weta[tid*8 + i] = f[i];
        return;
    }
    __nv_bfloat16 hi[8], lo[8];
    #pragma unroll
    for (int i = 0; i < 8; i++) {
        hi[i] = __float2bfloat16_rn(f[i]);
        lo[i] = __float2bfloat16_rn(f[i] - __bfloat162float(hi[i]));
    }
    union { uint4 q[3]; __nv_bfloat162 h2[12]; } pk;
    #pragma unroll
    for (int j = 0; j < 4; j++) {   // B pattern per k: (hi, hi, lo)
        pk.h2[3*j+0] = __halves2bfloat162(hi[2*j],   hi[2*j]);
        pk.h2[3*j+1] = __halves2bfloat162(lo[2*j],   hi[2*j+1]);
        pk.h2[3*j+2] = __halves2bfloat162(hi[2*j+1], lo[2*j+1]);
    }
    uint4* dst = (uint4*)(g_B3 + (size_t)n * KP) + tid * 3;
    dst[0] = pk.q[0]; dst[1] = pk.q[1]; dst[2] = pk.q[2];
}

// ----------------- K1: fused HMMA GEMM + in-loop A conversion + LN stats + epilogue -----------------
// BM=128, BN=64; per stage: LDG 128x16 fp32 of H (reg prefetch depth 2),
// convert to 128x48 bf16 tripled into sA; B tile via cp.async (double buffer).
__global__ void __launch_bounds__(256) mma_kernel(const float* __restrict__ H) {
    __shared__ __align__(16) __nv_bfloat16 sA[2][128*STR];  // 28672 B
    __shared__ __align__(16) __nv_bfloat16 sB[2][64*STR];   // 14336 B
    __shared__ float smu[128], srs[128];
    const int tid = threadIdx.x;
    const int wid = tid >> 5, lane = tid & 31;
    const int warp_m = wid & 3, warp_n = wid >> 2;
    const int g = lane >> 2, t = lane & 3;
    const int m0 = blockIdx.y * 128, n0 = blockIdx.x * 64;

    // A producer mapping: thread owns half a row per stage
    const int arow = tid >> 1, ahalf = tid & 1;
    const float* pA = H + (size_t)(m0 + arow) * HD + ahalf * 8;
    char* dAbase = (char*)sA[0] + arow * 112 + ahalf * 48;

    // B producer mapping: 384 16B-chunks per stage
    const int b1r = tid / 6, b1c = tid - b1r * 6;
    const int i2 = (tid < 128) ? tid + 256 : tid;
    const int b2r = i2 / 6, b2c = i2 - b2r * 6;
    const char* pB1 = (const char*)(g_B3 + (size_t)(n0 + b1r) * KP) + b1c * 16;
    const char* pB2 = (const char*)(g_B3 + (size_t)(n0 + b2r) * KP) + b2c * 16;
    const uint32_t sB_u = smem_u32(sB[0]);
    const uint32_t dB1 = sB_u + b1r * 112 + b1c * 16;
    const uint32_t dB2 = sB_u + b2r * 112 + b2c * 16;

    float acc[2][4][4];
    #pragma unroll
    for (int mi = 0; mi < 2; mi++)
        #pragma unroll
        for (int ni = 0; ni < 4; ni++)
            #pragma unroll
            for (int j = 0; j < 4; j++) acc[mi][ni][j] = 0.f;

    float sum_s = 0.f, sum_q = 0.f, dotw = 0.f;

    // prologue: A regs for stages 0,1 ; B stage 0 in flight
    float4 a0a = *(const float4*)(pA);
    float4 a0b = *(const float4*)(pA + 4);
    float4 a1a = *(const float4*)(pA + 16);
    float4 a1b = *(const float4*)(pA + 20);
    CP_ASYNC16(dB1, pB1);
    if (tid < 128) CP_ASYNC16(dB2, pB2);
    CP_COMMIT();

    for (int s = 0; s < STAGES; s++) {
        const int buf = s & 1;
        CP_WAIT0();                         // B(s) resident
        // ---- convert stage s A tile (regs -> smem), accumulate LN stats ----
        {
            float f[8] = {a0a.x, a0a.y, a0a.z, a0a.w, a0b.x, a0b.y, a0b.z, a0b.w};
            const float4 w0 = *(const float4*)(g_weta + s * 16 + ahalf * 8);
            const float4 w1 = *(const float4*)(g_weta + s * 16 + ahalf * 8 + 4);
            float wv[8] = {w0.x, w0.y, w0.z, w0.w, w1.x, w1.y, w1.z, w1.w};
            #pragma unroll
            for (int i = 0; i < 8; i++) {
                sum_s += f[i];
                sum_q += f[i] * f[i];
                dotw  += f[i] * wv[i];
            }
            __nv_bfloat16 hi[8], lo[8];
            #pragma unroll
            for (int i = 0; i < 8; i++) {
                hi[i] = __float2bfloat16_rn(f[i]);
                lo[i] = __float2bfloat16_rn(f[i] - __bfloat162float(hi[i]));
            }
            union { uint4 q[3]; __nv_bfloat162 h2[12]; } pk;
            #pragma unroll
            for (int j = 0; j < 4; j++) {   // A pattern per k: (hi, lo, hi)
                pk.h2[3*j+0] = __halves2bfloat162(hi[2*j],   lo[2*j]);
                pk.h2[3*j+1] = __halves2bfloat162(hi[2*j],   hi[2*j+1]);
                pk.h2[3*j+2] = __halves2bfloat162(lo[2*j+1], hi[2*j+1]);
            }
            uint4* dA = (uint4*)(dAbase + buf * (128 * STR * 2));
            dA[0] = pk.q[0]; dA[1] = pk.q[1]; dA[2] = pk.q[2];
        }
        __syncthreads();                    // sA[buf] + sB[buf] visible to all
        // ---- issue next B stage (opposite buffer is safe past the barrier) ----
        if (s + 1 < STAGES) {
            const uint32_t off = (buf ^ 1) * (64 * STR * 2);
            CP_ASYNC16(dB1 + off, pB1 + (size_t)(s + 1) * 96);
            if (tid < 128) CP_ASYNC16(dB2 + off, pB2 + (size_t)(s + 1) * 96);
        }
        CP_COMMIT();
        // ---- prefetch A regs for stage s+2 ----
        float4 a2a, a2b;
        if (s + 2 < STAGES) {
            a2a = *(const float4*)(pA + (size_t)(s + 2) * 16);
            a2b = *(const float4*)(pA + (size_t)(s + 2) * 16 + 4);
        } else { a2a = a1a; a2b = a1b; }
        // ---- consume: 3 k-steps of mma ----
        const __nv_bfloat16* bA = sA[buf];
        const __nv_bfloat16* bB = sB[buf];
        #pragma unroll
        for (int kk = 0; kk < 3; kk++) {
            uint32_t a[2][4], b[4][2];
            #pragma unroll
            for (int mi = 0; mi < 2; mi++) {
                const __nv_bfloat16* p = bA + (warp_m*32 + mi*16 + g) * STR + kk*16 + t*2;
                a[mi][0] = *(const uint32_t*)(p);
                a[mi][1] = *(const uint32_t*)(p + 8*STR);
                a[mi][2] = *(const uint32_t*)(p + 8);
                a[mi][3] = *(const uint32_t*)(p + 8*STR + 8);
            }
            #pragma unroll
            for (int ni = 0; ni < 4; ni++) {
                const __nv_bfloat16* p = bB + (warp_n*32 + ni*8 + g) * STR + kk*16 + t*2;
                b[ni][0] = *(const uint32_t*)(p);
                b[ni][1] = *(const uint32_t*)(p + 8);
            }
            #pragma unroll
            for (int mi = 0; mi < 2; mi++)
                #pragma unroll
                for (int ni = 0; ni < 4; ni++)
                    mma16816(acc[mi][ni], a[mi], b[ni]);
        }
        a0a = a1a; a0b = a1b; a1a = a2a; a1b = a2b;
    }

    // ---- finalize LN stats: pair-combine (tid, tid^1) owns one row ----
    {
        sum_s += __shfl_xor_sync(0xffffffffu, sum_s, 1);
        sum_q += __shfl_xor_sync(0xffffffffu, sum_q, 1);
        dotw  += __shfl_xor_sync(0xffffffffu, dotw, 1);
        if (ahalf == 0) {
            float mu = sum_s * (1.f / HD);
            float var = sum_q * (1.f / HD) - mu * mu;
            float rs = rsqrtf(var + 1e-5f);
            smu[arow] = mu;
            srs[arow] = rs;
            if (blockIdx.x == 0)
                g_eta[m0 + arow] = rs * (dotw - mu * g_gW[256]) + g_bproj[256];
        }
    }
    __syncthreads();

    // ---- epilogue: folded layernorm + column routing ----
    #pragma unroll
    for (int mi = 0; mi < 2; mi++) {
        int lr0 = warp_m*32 + mi*16 + g;
        int lr1 = lr0 + 8;
        int r0 = m0 + lr0, r1 = m0 + lr1;
        float mu0 = smu[lr0], rs0 = srs[lr0];
        float mu1 = smu[lr1], rs1 = srs[lr1];
        #pragma unroll
        for (int ni = 0; ni < 4; ni++) {
            int c0 = n0 + warp_n*32 + ni*8 + t*2;
            #pragma unroll
            for (int j = 0; j < 2; j++) {
                int col = c0 + j;
                float gw = g_gW[col], bp = g_bproj[col];
                float v0 = rs0 * (acc[mi][ni][j]     - mu0 * gw) + bp;
                float v1 = rs1 * (acc[mi][ni][2 + j] - mu1 * gw) + bp;
                if (col < 128) {
                    g_Hmem[(size_t)r0*DD + col] = v0;
                    g_Hmem[(size_t)r1*DD + col] = v1;
                } else {
                    g_Qr[(size_t)r0*DD + col - 128] = v0;
                    g_Qr[(size_t)r1*DD + col - 128] = v1;
                }
            }
        }
    }
}

// ----------------- K3: per-segment summary softmax + Z_seg + eta_seg -----------------
__global__ void seg_kernel(const float* __restrict__ sum_q) {
    __shared__ float Hs[LLEN*129];
    __shared__ float qs[DD];
    __shared__ float sc[LLEN];
    int seg = blockIdx.x;
    int tid = threadIdx.x;   // 128
    int base = seg * LLEN;
    for (int l = 0; l < LLEN; l++)
        Hs[l*129 + tid] = g_Hmem[(size_t)(base + l)*DD + tid];
    qs[tid] = sum_q[tid];
    __syncthreads();
    if (tid < LLEN) {
        float s = 0.f;
        for (int d = 0; d < DD; d++) s += qs[d] * Hs[tid*129 + d];
        sc[tid] = s * SCALEF;
    }
    __syncthreads();
    float mx = -3.4e38f;
    for (int l = 0; l < LLEN; l++) mx = fmaxf(mx, sc[l]);
    __syncthreads();
    if (tid < LLEN) sc[tid] = expf(sc[tid] - mx);
    __syncthreads();
    float sum = 0.f;
    for (int l = 0; l < LLEN; l++) sum += sc[l];
    float inv = 1.f / sum;
    float z = 0.f;
    for (int l = 0; l < LLEN; l++) z += sc[l] * Hs[l*129 + tid];
    g_Z[seg*DD + tid] = z * inv;
    __syncthreads();
    if (tid < LLEN) sc[tid] = g_eta[base + tid];
    __syncthreads();
    float em = -3.4e38f;
    for (int l = 0; l < LLEN; l++) em = fmaxf(em, sc[l]);
    if (tid == 0) g_etaseg[seg] = 1.f / (1.f + expf(-em));
}

// ----------------- K4: A = softmax(Z . M * scale * exp(temp)) -----------------
__global__ void scoreA_kernel(const float* __restrict__ M, const float* __restrict__ temp) {
    __shared__ float Zs[DD];
    __shared__ float sbuf[DD];
    int seg = blockIdx.x;
    int tid = threadIdx.x;
    int b = seg >> 6;
    Zs[tid] = g_Z[seg*DD + tid];
    __syncthreads();
    const float* mrow = M + (size_t)(b*DD + tid) * DD;
    float s = 0.f;
    for (int d = 0; d < DD; d++) s += Zs[d] * mrow[d];
    s *= SCALEF * expf(temp[0]);
    sbuf[tid] = s;
    __syncthreads();
    float mx = -3.4e38f;
    for (int k = 0; k < DD; k++) mx = fmaxf(mx, sbuf[k]);
    __syncthreads();
    float e = expf(s - mx);
    sbuf[tid] = e;
    __syncthreads();
    float sum = 0.f;
    for (int k = 0; k < DD; k++) sum += sbuf[k];
    g_A[seg*DD + tid] = e / sum;
}

// ----------------- K5: DeltaM, M_new, Mn, norm_sq partials -----------------
__global__ void update_kernel(const float* __restrict__ M, const float* __restrict__ eta_ch) {
    __shared__ float ae[LLEN];
    __shared__ float etas[LLEN];
    __shared__ float red[4];
    int k = blockIdx.x, b = blockIdx.y;
    int tid = threadIdx.x;
    if (tid < SSEG) {
        float e = g_etaseg[b*SSEG + tid];
        etas[tid] = e;
        ae[tid] = g_A[(size_t)(b*SSEG + tid)*DD + k] * e;
    }
    __syncthreads();
    float eavg = 0.f;
    for (int s = 0; s < SSEG; s++) eavg += etas[s];
    eavg *= (1.f / SSEG);
    float delta = 0.f;
    for (int s = 0; s < SSEG; s++)
        delta += ae[s] * g_Z[(size_t)(b*SSEG + s)*DD + tid];
    float mold = M[(size_t)(b*DD + k)*DD + tid];
    float gate = eavg * (1.f / (1.f + expf(-eta_ch[tid])));
    float mnew = (1.f - gate) * mold + delta * (1.f / SSEG);

    float ns = blockSumG(delta * delta, red);
    if (tid == 0) g_normp[b*DD + k] = ns;
    float nn = blockSumG(mnew * mnew, red);
    float inv = 1.f / fmaxf(sqrtf(nn), 1e-12f);
    size_t idx = (size_t)(b*DD + k)*DD + tid;
    g_Mnew[idx] = mnew;
    g_Mn[idx]   = mnew * inv;
}

// ----------------- K6: diversity loss partials -----------------
__global__ void div_kernel() {
    __shared__ float mks[DD];
    __shared__ float red[4];
    int k = blockIdx.x, b = blockIdx.y;
    int tid = threadIdx.x;
    mks[tid] = g_Mn[(size_t)(b*DD + k)*DD + tid];
    __syncthreads();
    const float* mj = g_Mn + (size_t)(b*DD + tid)*DD;
    float s = 0.f;
    for (int d = 0; d < DD; d++) s += mks[d] * mj[d];
    float v = (tid == k) ? 0.f : s * s;
    float tot = blockSumG(v, red);
    if (tid == 0) g_divp[b*DD + k] = tot;
}

// ----------------- K7: finalize loss -----------------
__global__ void finalize_kernel(float* __restrict__ out, int out_size) {
    __shared__ float red[8];
    float n = 0.f, d = 0.f;
    for (int i = threadIdx.x; i < BATCH*DD; i += 256) {
        n += g_normp[i];
        d += g_divp[i];
    }
    n = blockSumG(n, red);
    d = blockSumG(d, red);
    if (threadIdx.x == 0) {
        float norm_sq = n * (1.f / SSEG);
        float div = d / (float)(BATCH*DD*DD);
        out[out_size - 1] = norm_sq * 0.01f + div * 0.1f;
    }
}

// ----------------- K8: read attention, 4-token batched -----------------
__global__ void read_kernel(float* __restrict__ out) {
    extern __shared__ float sm[];
    float* Ms = sm;               // 128*129
    float* q4 = sm + DD*129;      // 4*128
    float* a4 = q4 + 4*DD;        // 4*128
    int tid = threadIdx.x;        // 128
    int t0 = blockIdx.x * 32;
    int b = t0 >> 12;
    for (int k = 0; k < DD; k++)
        Ms[k*129 + tid] = g_Mnew[(size_t)(b*DD + k)*DD + tid];
    __syncthreads();
    for (int tk = 0; tk < 32; tk += 4) {
        #pragma unroll
        for (int j = 0; j < 4; j++)
            q4[j*DD + tid] = g_Qr[(size_t)(t0 + tk + j)*DD + tid];
        __syncthreads();
        float s0 = 0.f, s1 = 0.f, s2 = 0.f, s3 = 0.f;
        #pragma unroll 4
        for (int d = 0; d < DD; d++) {
            float m = Ms[tid*129 + d];
            s0 += q4[d] * m;
            s1 += q4[DD + d] * m;
            s2 += q4[2*DD + d] * m;
            s3 += q4[3*DD + d] * m;
        }
        a4[tid]        = s0 * 2.f;
        a4[DD + tid]   = s1 * 2.f;
        a4[2*DD + tid] = s2 * 2.f;
        a4[3*DD + tid] = s3 * 2.f;
        __syncthreads();
        {   // warp w handles token tk+w softmax over 128 scores
            int w = tid >> 5, lane = tid & 31;
            float v0 = a4[w*DD + lane],      v1 = a4[w*DD + lane + 32];
            float v2 = a4[w*DD + lane + 64], v3 = a4[w*DD + lane + 96];
            float mx = fmaxf(fmaxf(v0, v1), fmaxf(v2, v3));
            #pragma unroll
            for (int o = 16; o; o >>= 1) mx = fmaxf(mx, __shfl_xor_sync(0xffffffffu, mx, o));
            float e0 = expf(v0 - mx), e1 = expf(v1 - mx), e2 = expf(v2 - mx), e3 = expf(v3 - mx);
            float su = e0 + e1 + e2 + e3;
            #pragma unroll
            for (int o = 16; o; o >>= 1) su += __shfl_xor_sync(0xffffffffu, su, o);
            float inv = 1.f / su;
            a4[w*DD + lane]      = e0 * inv;
            a4[w*DD + lane + 32] = e1 * inv;
            a4[w*DD + lane + 64] = e2 * inv;
            a4[w*DD + lane + 96] = e3 * inv;
        }
        __syncthreads();
        float c0 = 0.f, c1 = 0.f, c2 = 0.f, c3 = 0.f;
        #pragma unroll 4
        for (int k = 0; k < DD; k++) {
            float m = Ms[k*129 + tid];
            c0 += a4[k] * m;
            c1 += a4[DD + k] * m;
            c2 += a4[2*DD + k] * m;
            c3 += a4[3*DD + k] * m;
        }
        out[(size_t)(t0 + tk)*DD + tid]     = c0;
        out[(size_t)(t0 + tk + 1)*DD + tid] = c1;
        out[(size_t)(t0 + tk + 2)*DD + tid] = c2;
        out[(size_t)(t0 + tk + 3)*DD + tid] = c3;
        __syncthreads();
    }
}

// ----------------- launch -----------------
extern "C" void kernel_launch(void* const* d_in, const int* in_sizes, int n_in,
                              void* d_out, int out_size) {
    const float* H       = (const float*)d_in[0];
    const float* M       = (const float*)d_in[1];
    const float* ln_g    = (const float*)d_in[2];
    const float* ln_b    = (const float*)d_in[3];
    const float* W_eta_w = (const float*)d_in[4];
    const float* W_eta_b = (const float*)d_in[5];
    const float* sum_q   = (const float*)d_in[6];
    const float* sp_w    = (const float*)d_in[7];
    const float* sp_b    = (const float*)d_in[8];
    const float* eta_ch  = (const float*)d_in[9];
    const float* temp    = (const float*)d_in[10];
    const float* W_qkv   = (const float*)d_in[11];
    float* out = (float*)d_out;

    int smem_read = (DD*129 + 8*DD) * (int)sizeof(float);
    cudaFuncSetAttribute(read_kernel, cudaFuncAttributeMaxDynamicSharedMemorySize, smem_read);

    bprep_kernel<<<NB + 1, 256>>>(ln_g, ln_b, sp_w, W_qkv, W_eta_w, W_eta_b, sp_b);
    mma_kernel<<<dim3(NB/64, NT/128), 256>>>(H);
    seg_kernel<<<NSEG, 128>>>(sum_q);
    scoreA_kernel<<<NSEG, 128>>>(M, temp);
    update_kernel<<<dim3(DD, BATCH), 128>>>(M, eta_ch);
    div_kernel<<<dim3(DD, BATCH), 128>>>();
    finalize_kernel<<<1, 256>>>(out, out_size);
    read_kernel<<<NT/32, 128, smem_read>>>(out);
}